// round 1
// baseline (speedup 1.0000x reference)
#include <cuda_runtime.h>

typedef unsigned long long u64;
typedef unsigned int u32;

#define NA 8192
#define NB 8192
#define NLAYERS 16
#define CHUNKS 64
#define ROWS_PER_CHUNK (NA / CHUNKS)   // 128

// ---------------- scratch (static device arrays; no allocation) ----------------
__device__ float d_la[NA];
__device__ float d_lb[NB];
__device__ float d_f[NA];
__device__ float d_g[NB];
__device__ float d_gk[NB];          // g[j] / (eps*ln2)
__device__ u64   d_fk2[NA];         // (f[i]/(eps*ln2)) packed in both halves
__device__ float d_partial[CHUNKS * NB];

// ---------------- packed f32x2 helpers ----------------
__device__ __forceinline__ u64 fma2(u64 a, u64 b, u64 c) {
    u64 d;
    asm("fma.rn.f32x2 %0,%1,%2,%3;" : "=l"(d) : "l"(a), "l"(b), "l"(c));
    return d;
}
__device__ __forceinline__ u64 add2(u64 a, u64 b) {
    u64 d;
    asm("add.rn.f32x2 %0,%1,%2;" : "=l"(d) : "l"(a), "l"(b));
    return d;
}
__device__ __forceinline__ u64 pack2(float x) {
    u32 b = __float_as_uint(x);
    return (u64)b | ((u64)b << 32);
}

// packed exp2 constants
struct EC {
    u64 p5, p4, p3, p2, p1, p0;
};
__device__ __forceinline__ EC make_ec() {
    EC e;
    e.p5 = pack2(1.33335581465e-3f);
    e.p4 = pack2(9.61812910763e-3f);
    e.p3 = pack2(5.55041086648e-2f);
    e.p2 = pack2(2.40226506959e-1f);
    e.p1 = pack2(6.93147180560e-1f);
    e.p0 = pack2(1.0f);
    return e;
}

#define MAG2  0x4B4000004B400000ull   //  12582912.0f x2  (1.5*2^23)
#define NMAG2 0xCB400000CB400000ull   // -12582912.0f x2
#define NONE2 0xBF800000BF800000ull   // -1.0f x2

// 2^p for both packed lanes; accumulate the two scalar results.
// Valid for p in roughly [-120, +120]; our p stays within ~[-60, +20].
__device__ __forceinline__ void exp2acc(u64 p, const EC& ec, float& a0, float& a1) {
    u64 t = add2(p, MAG2);            // magic round-to-nearest-int (per lane)
    u64 u = add2(t, NMAG2);           // u = round(p)  (exact)
    u64 f = fma2(u, NONE2, p);        // f = p - u  in [-0.5, 0.5]
    u64 r = fma2(ec.p5, f, ec.p4);    // degree-5 Horner: 2^f
    r = fma2(r, f, ec.p3);
    r = fma2(r, f, ec.p2);
    r = fma2(r, f, ec.p1);
    r = fma2(r, f, ec.p0);
    u32 tl = (u32)t, th = (u32)(t >> 32);
    u32 rl = (u32)r, rh = (u32)(r >> 32);
    // (bits(t) << 23) == (i << 23) exactly since low 9 bits of 0x4B400000 are 0.
    a0 += __uint_as_float((tl << 23) + rl);
    a1 += __uint_as_float((th << 23) + rh);
}

// ---------------- setup: log(alpha), log(beta), gk = 0 ----------------
__global__ void __launch_bounds__(256) setup_kernel(const float* __restrict__ alpha,
                                                    const float* __restrict__ beta) {
    int i = blockIdx.x * 256 + threadIdx.x;
    if (i < NA) d_la[i] = logf(alpha[i]);
    if (i < NB) {
        d_lb[i] = logf(beta[i]);
        d_gk[i] = 0.0f;
    }
}

// ---------------- row pass: f_i = eps*(la_i - ln(sum_j 2^(gk_j - C_ij*k))) ----------------
__global__ void __launch_bounds__(256) row_pass(const float* __restrict__ C,
                                                const float* __restrict__ epsp) {
    const int i = blockIdx.x;
    const int t = threadIdx.x;
    const float eps = __ldg(epsp);
    const float kk = 1.0f / (eps * 0.69314718056f);  // 1/(eps*ln2)
    const u64 negk2 = pack2(-kk);
    const EC ec = make_ec();

    const ulonglong2* __restrict__ Crow = (const ulonglong2*)(C + (size_t)i * NB);
    const ulonglong2* __restrict__ GK = (const ulonglong2*)d_gk;

    float a0 = 0.f, a1 = 0.f, a2 = 0.f, a3 = 0.f;
#pragma unroll
    for (int it = 0; it < NB / (4 * 256); ++it) {  // 8 iterations, float4 granularity
        int idx = t + it * 256;
        ulonglong2 cc = Crow[idx];
        ulonglong2 gg = GK[idx];
        u64 p0 = fma2(cc.x, negk2, gg.x);
        u64 p1 = fma2(cc.y, negk2, gg.y);
        exp2acc(p0, ec, a0, a1);
        exp2acc(p1, ec, a2, a3);
    }
    float s = (a0 + a1) + (a2 + a3);
#pragma unroll
    for (int o = 16; o > 0; o >>= 1) s += __shfl_down_sync(0xffffffffu, s, o);

    __shared__ float red[8];
    if ((t & 31) == 0) red[t >> 5] = s;
    __syncthreads();
    if (t == 0) {
        float tot = 0.f;
#pragma unroll
        for (int w = 0; w < 8; ++w) tot += red[w];
        float fi = eps * (d_la[i] - logf(tot));
        d_f[i] = fi;
        d_fk2[i] = pack2(fi * kk);
    }
}

// ---------------- column pass: partial[chunk][j] = sum_{i in chunk} 2^(fk_i - C_ij*k) ----------------
__global__ void __launch_bounds__(256) col_pass(const float* __restrict__ C,
                                                const float* __restrict__ epsp) {
    const float eps = __ldg(epsp);
    const float kk = 1.0f / (eps * 0.69314718056f);
    const u64 negk2 = pack2(-kk);
    const EC ec = make_ec();

    const int j2 = blockIdx.x * 512 + threadIdx.x * 2;  // this thread's column pair
    const int i0 = blockIdx.y * ROWS_PER_CHUNK;

    const u64* __restrict__ Cp = (const u64*)C;  // pairs of floats
    size_t base = (size_t)i0 * (NB / 2) + (j2 >> 1);

    float a0 = 0.f, a1 = 0.f;
#pragma unroll 4
    for (int r = 0; r < ROWS_PER_CHUNK; ++r) {
        u64 cc = Cp[base + (size_t)r * (NB / 2)];
        u64 fk = d_fk2[i0 + r];   // warp-uniform broadcast, L1 hit
        u64 p = fma2(cc, negk2, fk);
        exp2acc(p, ec, a0, a1);
    }
    ((float2*)(d_partial + (size_t)blockIdx.y * NB))[j2 >> 1] = make_float2(a0, a1);
}

// ---------------- combine: g_j = eps*(lb_j - ln(sum_chunks partial)) ----------------
__global__ void __launch_bounds__(256) combine_kernel(const float* __restrict__ epsp) {
    int j = blockIdx.x * 256 + threadIdx.x;
    const float eps = __ldg(epsp);
    const float kk = 1.0f / (eps * 0.69314718056f);
    float s = 0.f;
#pragma unroll
    for (int c = 0; c < CHUNKS; ++c) s += d_partial[(size_t)c * NB + j];
    float gj = eps * (d_lb[j] - logf(s));
    d_g[j] = gj;
    d_gk[j] = gj * kk;
}

// ---------------- writeout: out = concat(f, g) ----------------
__global__ void __launch_bounds__(256) writeout_kernel(float* __restrict__ out, int out_size) {
    int i = blockIdx.x * 256 + threadIdx.x;
    if (i < NA) {
        if (i < out_size) out[i] = d_f[i];
    } else {
        int j = i - NA;
        if (NA + j < out_size) out[NA + j] = d_g[j];
    }
}

extern "C" void kernel_launch(void* const* d_in, const int* in_sizes, int n_in,
                              void* d_out, int out_size) {
    const float* alpha = (const float*)d_in[0];
    const float* beta  = (const float*)d_in[1];
    const float* C     = (const float*)d_in[2];
    const float* eps   = (const float*)d_in[3];

    setup_kernel<<<(NA + 255) / 256, 256>>>(alpha, beta);
    for (int l = 0; l < NLAYERS; ++l) {
        row_pass<<<NA, 256>>>(C, eps);
        col_pass<<<dim3(NB / 512, CHUNKS), 256>>>(C, eps);
        combine_kernel<<<NB / 256, 256>>>(eps);
    }
    writeout_kernel<<<(NA + NB + 255) / 256, 256>>>((float*)d_out, out_size);
}

// round 3
// speedup vs baseline: 1.6138x; 1.6138x over previous
#include <cuda_runtime.h>

typedef unsigned int u32;

#define NA 8192
#define NB 8192
#define NLAYERS 16

#define RP_ROWS 16
#define RP_THREADS 512
#define RP_BLOCKS (NA / RP_ROWS)       // 512

#define CP_THREADS 256
#define CP_JBLK (CP_THREADS * 16)      // 4096 cols per block
#define CP_CHUNK 128                   // rows per block
#define CP_GX (NB / CP_JBLK)           // 2
#define CP_GY (NA / CP_CHUNK)          // 64

// ---------------- static device scratch (no allocation) ----------------
__device__ __align__(128) unsigned char d_M[(size_t)NA * NB];  // 64 MB, L2-resident
__device__ float d_u[NA];
__device__ float d_v[NB];
__device__ float d_part[(size_t)CP_GY * NB];

// ---------------- custom uf8 codec: value = 2^(e-15) * (1 + m/16) ----------------
// decode: fp32 bits = (byte << 19) + 0x38000000  (bias 127-15=112 -> 112<<23)
__device__ __forceinline__ float dec8(u32 w, int sh) {
    u32 b = (w >> (sh * 8)) & 0xFFu;
    return __uint_as_float((b << 19) + 0x38000000u);
}
// encode with round-to-nearest on the 4-bit mantissa (carry propagates into exp)
__device__ __forceinline__ u32 enc8(float m) {
    int v = (int)(__float_as_uint(m) + 0x40000u) - 0x38000000;
    v >>= 19;
    v = v < 0 ? 0 : (v > 255 ? 255 : v);
    return (u32)v;
}

// ---------------- encode M = exp(-C/eps) to uf8; init v = 1 ----------------
__global__ void __launch_bounds__(256) encode_kernel(const float* __restrict__ C,
                                                     const float* __restrict__ epsp) {
    const float inv = -1.0f / __ldg(epsp);
    size_t idx = (size_t)blockIdx.x * 256 + threadIdx.x;  // one per 8 elements
    if (idx < NB) d_v[idx] = 1.0f;
    const float4* Cp = (const float4*)C;
    float4 c0 = Cp[idx * 2 + 0];
    float4 c1 = Cp[idx * 2 + 1];
    u32 lo = enc8(__expf(c0.x * inv)) | (enc8(__expf(c0.y * inv)) << 8) |
             (enc8(__expf(c0.z * inv)) << 16) | (enc8(__expf(c0.w * inv)) << 24);
    u32 hi = enc8(__expf(c1.x * inv)) | (enc8(__expf(c1.y * inv)) << 8) |
             (enc8(__expf(c1.z * inv)) << 16) | (enc8(__expf(c1.w * inv)) << 24);
    ((uint2*)d_M)[idx] = make_uint2(lo, hi);
}

// ---------------- row pass: u_i = alpha_i / sum_j M_ij v_j ----------------
__global__ void __launch_bounds__(RP_THREADS) row_pass(const float* __restrict__ alpha) {
    const int t = threadIdx.x;
    const int i0 = blockIdx.x * RP_ROWS;

    // this thread's 16 v values (cols 16t .. 16t+15), held in registers
    const float4* vp = (const float4*)d_v;
    float4 va = vp[t * 4 + 0], vb = vp[t * 4 + 1], vc = vp[t * 4 + 2], vd = vp[t * 4 + 3];

    float acc[RP_ROWS];
#pragma unroll
    for (int r = 0; r < RP_ROWS; ++r) acc[r] = 0.0f;

    const uint4* Mp = (const uint4*)d_M;
    size_t base = (size_t)i0 * (NB / 16) + t;

#pragma unroll 4
    for (int r = 0; r < RP_ROWS; ++r) {
        uint4 m = Mp[base + (size_t)r * (NB / 16)];
        float s0 = dec8(m.x, 0) * va.x + dec8(m.x, 1) * va.y +
                   dec8(m.x, 2) * va.z + dec8(m.x, 3) * va.w;
        float s1 = dec8(m.y, 0) * vb.x + dec8(m.y, 1) * vb.y +
                   dec8(m.y, 2) * vb.z + dec8(m.y, 3) * vb.w;
        float s2 = dec8(m.z, 0) * vc.x + dec8(m.z, 1) * vc.y +
                   dec8(m.z, 2) * vc.z + dec8(m.z, 3) * vc.w;
        float s3 = dec8(m.w, 0) * vd.x + dec8(m.w, 1) * vd.y +
                   dec8(m.w, 2) * vd.z + dec8(m.w, 3) * vd.w;
        acc[r] = (s0 + s1) + (s2 + s3);
    }

    // cross-thread reduction: 8 rows at a time through smem
    __shared__ float sred[8][RP_THREADS];
    __shared__ float sfin[8][2];
#pragma unroll
    for (int g = 0; g < RP_ROWS / 8; ++g) {
        __syncthreads();
#pragma unroll
        for (int rr = 0; rr < 8; ++rr) sred[rr][t] = acc[g * 8 + rr];
        __syncthreads();
        int rr = t >> 6;   // 0..7
        int b = t & 63;
        float s = 0.0f;
#pragma unroll
        for (int k = 0; k < 8; ++k) s += sred[rr][b + 64 * k];
#pragma unroll
        for (int o = 16; o > 0; o >>= 1) s += __shfl_down_sync(0xffffffffu, s, o);
        if ((t & 31) == 0) sfin[rr][b >> 5] = s;
        __syncthreads();
        if (t < 8) {
            int row = i0 + g * 8 + t;
            d_u[row] = alpha[row] / (sfin[t][0] + sfin[t][1]);
        }
    }
}

// ---------------- col pass: part[chunk][j] = sum_{i in chunk} M_ij u_i ----------------
__global__ void __launch_bounds__(CP_THREADS) col_pass() {
    const int t = threadIdx.x;
    const int i0 = blockIdx.y * CP_CHUNK;
    const int j16 = blockIdx.x * CP_THREADS + t;  // uint4 index within a row

    const uint4* Mp = (const uint4*)d_M;
    size_t base = (size_t)i0 * (NB / 16) + j16;

    float a[16];
#pragma unroll
    for (int k = 0; k < 16; ++k) a[k] = 0.0f;

#pragma unroll 4
    for (int r = 0; r < CP_CHUNK; ++r) {
        uint4 m = Mp[base + (size_t)r * (NB / 16)];
        float ui = __ldg(&d_u[i0 + r]);
        a[0] += dec8(m.x, 0) * ui;  a[1] += dec8(m.x, 1) * ui;
        a[2] += dec8(m.x, 2) * ui;  a[3] += dec8(m.x, 3) * ui;
        a[4] += dec8(m.y, 0) * ui;  a[5] += dec8(m.y, 1) * ui;
        a[6] += dec8(m.y, 2) * ui;  a[7] += dec8(m.y, 3) * ui;
        a[8] += dec8(m.z, 0) * ui;  a[9] += dec8(m.z, 1) * ui;
        a[10] += dec8(m.z, 2) * ui; a[11] += dec8(m.z, 3) * ui;
        a[12] += dec8(m.w, 0) * ui; a[13] += dec8(m.w, 1) * ui;
        a[14] += dec8(m.w, 2) * ui; a[15] += dec8(m.w, 3) * ui;
    }

    float4* P = (float4*)(d_part + (size_t)blockIdx.y * NB);
    int j4 = j16 * 4;
    P[j4 + 0] = make_float4(a[0], a[1], a[2], a[3]);
    P[j4 + 1] = make_float4(a[4], a[5], a[6], a[7]);
    P[j4 + 2] = make_float4(a[8], a[9], a[10], a[11]);
    P[j4 + 3] = make_float4(a[12], a[13], a[14], a[15]);
}

// ---------------- combine: v_j = beta_j / sum_chunks part ----------------
__global__ void __launch_bounds__(256) combine_kernel(const float* __restrict__ beta) {
    int j = blockIdx.x * 256 + threadIdx.x;
    float s = 0.0f;
#pragma unroll
    for (int c = 0; c < CP_GY; ++c) s += d_part[(size_t)c * NB + j];
    d_v[j] = beta[j] / s;
}

// ---------------- writeout: f = eps*ln u, g = eps*ln v ----------------
__global__ void __launch_bounds__(256) writeout_kernel(float* __restrict__ out, int n,
                                                       const float* __restrict__ epsp) {
    int i = blockIdx.x * 256 + threadIdx.x;
    float eps = __ldg(epsp);
    if (i < NA) {
        if (i < n) out[i] = eps * logf(d_u[i]);
    } else if (i < NA + NB) {
        if (i < n) out[i] = eps * logf(d_v[i - NA]);
    }
}

extern "C" void kernel_launch(void* const* d_in, const int* in_sizes, int n_in,
                              void* d_out, int out_size) {
    const float* alpha = (const float*)d_in[0];
    const float* beta  = (const float*)d_in[1];
    const float* C     = (const float*)d_in[2];
    const float* eps   = (const float*)d_in[3];

    encode_kernel<<<(int)(((size_t)NA * NB / 8) / 256), 256>>>(C, eps);
    for (int l = 0; l < NLAYERS; ++l) {
        row_pass<<<RP_BLOCKS, RP_THREADS>>>(alpha);
        col_pass<<<dim3(CP_GX, CP_GY), CP_THREADS>>>();
        combine_kernel<<<NB / 256, 256>>>(beta);
    }
    writeout_kernel<<<(NA + NB + 255) / 256, 256>>>((float*)d_out, out_size, eps);
}